// round 1
// baseline (speedup 1.0000x reference)
#include <cuda_runtime.h>

#define C_IN  32
#define C_OUT 64
#define KNUM  8
#define TILE  1024
#define EPS   1e-5f

// Scratch for cross-kernel reduction results (allocation-free per rules).
__device__ float g_sum[C_OUT];
__device__ float g_sumsq[C_OUT];
__device__ float g_a[C_OUT];
__device__ float g_b[C_OUT];

// ---------------------------------------------------------------------------
// Pass A: sparse conv + scatter.
// Block = 256 threads = 8 warps. Each block grabs a tile of TILE voxels,
// bins them by k_idx in shared memory, then warp j processes bin j with
// W[j] resident in registers (lane handles channels 2*lane, 2*lane+1).
// Accumulates into d_out via float2 global atomics (RED.64).
// ---------------------------------------------------------------------------
__global__ void __launch_bounds__(256, 2)
conv_scatter(const float* __restrict__ x,
             const float* __restrict__ W,
             const int*   __restrict__ kidx,
             const int*   __restrict__ oidx,
             float*       __restrict__ out,
             int n)
{
    __shared__ int bins[KNUM][TILE];
    __shared__ int cnts[KNUM];

    const int tid  = threadIdx.x;
    const int lane = tid & 31;
    const int wid  = tid >> 5;          // warp id == kernel offset j

    // Zero stat accumulators once per launch (written only by later kernels).
    if (blockIdx.x == 0 && tid < C_OUT) { g_sum[tid] = 0.f; g_sumsq[tid] = 0.f; }

    // Load W[wid][:, 2*lane : 2*lane+2] into registers: 64 floats per lane.
    float w0[C_IN], w1[C_IN];
    {
        const float2* Wj = (const float2*)(W + wid * (C_IN * C_OUT));
        #pragma unroll
        for (int k = 0; k < C_IN; ++k) {
            float2 t = Wj[k * (C_OUT / 2) + lane];
            w0[k] = t.x; w1[k] = t.y;
        }
    }

    const int tileBase = blockIdx.x * TILE;

    if (tid < KNUM) cnts[tid] = 0;
    __syncthreads();

    #pragma unroll
    for (int u = 0; u < TILE / 256; ++u) {
        int i = tileBase + u * 256 + tid;
        if (i < n) {
            int k   = kidx[i];
            int pos = atomicAdd(&cnts[k], 1);
            bins[k][pos] = i;
        }
    }
    __syncthreads();

    const int cnt = cnts[wid];
    for (int p = 0; p < cnt; ++p) {
        int   i  = bins[wid][p];
        float xv = x[i * C_IN + lane];        // coalesced 128B row read
        int   o  = oidx[i];                   // broadcast load

        float a0 = 0.f, a1 = 0.f;
        #pragma unroll
        for (int k = 0; k < C_IN; ++k) {
            float v = __shfl_sync(0xffffffffu, xv, k);
            a0 = fmaf(v, w0[k], a0);
            a1 = fmaf(v, w1[k], a1);
        }

        float2* dst = (float2*)(out + (size_t)o * C_OUT) + lane;
#if __CUDA_ARCH__ >= 900
        atomicAdd(dst, make_float2(a0, a1));   // RED.64 vector atomic
#else
        atomicAdd(&dst->x, a0);
        atomicAdd(&dst->y, a1);
#endif
    }
}

// ---------------------------------------------------------------------------
// Pass B: per-channel sum and sum-of-squares over the accumulated output.
// Stride is a multiple of 64, so each thread's channel (i & 63) is fixed.
// ---------------------------------------------------------------------------
__global__ void stats_pass(const float* __restrict__ out, int total)
{
    float s = 0.f, s2 = 0.f;
    const int stride = blockDim.x * gridDim.x;   // multiple of 64
    for (int i = blockIdx.x * blockDim.x + threadIdx.x; i < total; i += stride) {
        float v = out[i];
        s  += v;
        s2  = fmaf(v, v, s2);
    }

    __shared__ float sh1[C_OUT], sh2[C_OUT];
    const int c = threadIdx.x & 63;
    if (threadIdx.x < C_OUT) { sh1[threadIdx.x] = 0.f; sh2[threadIdx.x] = 0.f; }
    __syncthreads();
    atomicAdd(&sh1[c], s);
    atomicAdd(&sh2[c], s2);
    __syncthreads();
    if (threadIdx.x < C_OUT) {
        atomicAdd(&g_sum[threadIdx.x],   sh1[threadIdx.x]);
        atomicAdd(&g_sumsq[threadIdx.x], sh2[threadIdx.x]);
    }
}

// ---------------------------------------------------------------------------
// Pass C: finalize BN affine coefficients. Note the conv bias cancels:
//   final = (seg + bias - (mean_seg + bias)) * a + beta = (seg - mean_seg)*a + beta
// ---------------------------------------------------------------------------
__global__ void finalize_stats(const float* __restrict__ gamma,
                               const float* __restrict__ beta,
                               float inv_n)
{
    const int c = threadIdx.x;
    float mean = g_sum[c] * inv_n;
    float var  = g_sumsq[c] * inv_n - mean * mean;
    float a    = gamma[c] * rsqrtf(var + EPS);
    g_a[c] = a;
    g_b[c] = fmaf(-mean, a, beta[c]);
}

// ---------------------------------------------------------------------------
// Pass D: in-place normalize + ReLU.
// ---------------------------------------------------------------------------
__global__ void norm_relu(float* __restrict__ out, int total)
{
    const int c = threadIdx.x & 63;     // fixed per thread (stride % 64 == 0)
    const float a = g_a[c];
    const float b = g_b[c];
    const int stride = blockDim.x * gridDim.x;
    for (int i = blockIdx.x * blockDim.x + threadIdx.x; i < total; i += stride) {
        out[i] = fmaxf(fmaf(out[i], a, b), 0.f);
    }
}

// ---------------------------------------------------------------------------
// Launch. Inputs (metadata order): x, W, bias, gamma, beta, k_idx, out_idx,
// num_out. bias cancels out of BN; num_out = out_size / 64.
// ---------------------------------------------------------------------------
extern "C" void kernel_launch(void* const* d_in, const int* in_sizes, int n_in,
                              void* d_out, int out_size)
{
    const float* x     = (const float*)d_in[0];
    const float* W     = (const float*)d_in[1];
    const float* gamma = (const float*)d_in[3];
    const float* beta  = (const float*)d_in[4];
    const int*   kidx  = (const int*)d_in[5];
    const int*   oidx  = (const int*)d_in[6];

    const int n       = in_sizes[0] / C_IN;     // number of input voxels
    const int total   = out_size;               // num_out * 64
    const int num_out = total / C_OUT;

    cudaMemsetAsync(d_out, 0, (size_t)total * sizeof(float), 0);

    const int tiles = (n + TILE - 1) / TILE;
    conv_scatter<<<tiles, 256>>>(x, W, kidx, oidx, (float*)d_out, n);
    stats_pass<<<1184, 256>>>((const float*)d_out, total);
    finalize_stats<<<1, C_OUT>>>(gamma, beta, 1.0f / (float)num_out);
    norm_relu<<<1184, 256>>>((float*)d_out, total);
}

// round 2
// speedup vs baseline: 1.4113x; 1.4113x over previous
#include <cuda_runtime.h>

#define C_IN  32
#define C_OUT 64
#define KNUM  8
#define TILE  1024
#define EPS   1e-5f

__device__ float g_sum[C_OUT];
__device__ float g_sumsq[C_OUT];
__device__ float g_a[C_OUT];
__device__ float g_b[C_OUT];

__device__ __forceinline__ unsigned long long pack2(float lo, float hi) {
    unsigned long long r;
    asm("mov.b64 %0, {%1, %2};" : "=l"(r) : "f"(lo), "f"(hi));
    return r;
}
__device__ __forceinline__ void unpack2(unsigned long long v, float& lo, float& hi) {
    asm("mov.b64 {%0, %1}, %2;" : "=f"(lo), "=f"(hi) : "l"(v));
}
#define FMA_F32X2(acc, a, b) \
    asm("fma.rn.f32x2 %0, %1, %2, %0;" : "+l"(acc) : "l"(a), "l"(b))

// ---------------------------------------------------------------------------
// Pass A: sparse conv + scatter. 8 warps/block; warp j owns kernel offset j
// with W[j] packed in registers as k-pair f32x2 operands. Inner loop uses
// FFMA2 (fma.rn.f32x2): accumulator halves hold even-k / odd-k partials.
// Software-pipelined (prefetch next voxel) to hide x-row DRAM latency.
// ---------------------------------------------------------------------------
__global__ void __launch_bounds__(256, 2)
conv_scatter(const float* __restrict__ x,
             const float* __restrict__ W,
             const int*   __restrict__ kidx,
             const int*   __restrict__ oidx,
             float*       __restrict__ out,
             int n)
{
    __shared__ int bins[KNUM][TILE];
    __shared__ int cnts[KNUM];

    const int tid  = threadIdx.x;
    const int lane = tid & 31;
    const int wid  = tid >> 5;          // warp id == kernel offset j

    if (blockIdx.x == 0 && tid < C_OUT) { g_sum[tid] = 0.f; g_sumsq[tid] = 0.f; }

    // Pack W[wid] for this lane's channel pair (2*lane, 2*lane+1) across
    // k-pairs: wp0[p] = (W[2p][2l], W[2p+1][2l]), wp1[p] = same for 2l+1.
    unsigned long long wp0[C_IN / 2], wp1[C_IN / 2];
    {
        const float* Wj = W + wid * (C_IN * C_OUT);
        #pragma unroll
        for (int p = 0; p < C_IN / 2; ++p) {
            float2 ta = ((const float2*)(Wj + (2 * p)     * C_OUT))[lane];
            float2 tb = ((const float2*)(Wj + (2 * p + 1) * C_OUT))[lane];
            wp0[p] = pack2(ta.x, tb.x);
            wp1[p] = pack2(ta.y, tb.y);
        }
    }

    const int tileBase = blockIdx.x * TILE;

    if (tid < KNUM) cnts[tid] = 0;
    __syncthreads();

    #pragma unroll
    for (int u = 0; u < TILE / 256; ++u) {
        int i = tileBase + u * 256 + tid;
        if (i < n) {
            int k   = kidx[i];
            int pos = atomicAdd(&cnts[k], 1);
            bins[k][pos] = i;
        }
    }
    __syncthreads();

    const int cnt = cnts[wid];
    if (cnt == 0) return;

    // Prologue of the software pipeline.
    int   i0  = bins[wid][0];
    float xv  = x[(size_t)i0 * C_IN + lane];
    int   o   = oidx[i0];

    for (int p = 0; p < cnt; ++p) {
        // Prefetch next voxel (MLP=2) before the compute body.
        float xv_n = 0.f; int o_n = 0;
        if (p + 1 < cnt) {
            int i1 = bins[wid][p + 1];
            xv_n = x[(size_t)i1 * C_IN + lane];
            o_n  = oidx[i1];
        }

        unsigned long long acc0 = 0ull, acc1 = 0ull;
        #pragma unroll
        for (int q = 0; q < C_IN / 2; ++q) {
            float va = __shfl_sync(0xffffffffu, xv, 2 * q);
            float vb = __shfl_sync(0xffffffffu, xv, 2 * q + 1);
            unsigned long long vv = pack2(va, vb);
            FMA_F32X2(acc0, vv, wp0[q]);
            FMA_F32X2(acc1, vv, wp1[q]);
        }
        float a0l, a0h, a1l, a1h;
        unpack2(acc0, a0l, a0h);
        unpack2(acc1, a1l, a1h);
        float a0 = a0l + a0h;
        float a1 = a1l + a1h;

        float2* dst = (float2*)(out + (size_t)o * C_OUT) + lane;
        atomicAdd(dst, make_float2(a0, a1));   // RED.64

        xv = xv_n; o = o_n;
    }
}

// ---------------------------------------------------------------------------
// Pass B: per-channel sum / sum-of-squares, float4-vectorized.
// Grid*block is a multiple of 16 float4s => each thread's channel group fixed.
// ---------------------------------------------------------------------------
__global__ void stats_pass(const float4* __restrict__ out4, int n4)
{
    float4 s  = make_float4(0.f, 0.f, 0.f, 0.f);
    float4 s2 = make_float4(0.f, 0.f, 0.f, 0.f);
    const int start  = blockIdx.x * blockDim.x + threadIdx.x;
    const int stride = blockDim.x * gridDim.x;   // multiple of 16
    for (int i = start; i < n4; i += stride) {
        float4 v = out4[i];
        s.x += v.x; s.y += v.y; s.z += v.z; s.w += v.w;
        s2.x = fmaf(v.x, v.x, s2.x); s2.y = fmaf(v.y, v.y, s2.y);
        s2.z = fmaf(v.z, v.z, s2.z); s2.w = fmaf(v.w, v.w, s2.w);
    }

    __shared__ float sh1[C_OUT], sh2[C_OUT];
    if (threadIdx.x < C_OUT) { sh1[threadIdx.x] = 0.f; sh2[threadIdx.x] = 0.f; }
    __syncthreads();
    const int cg = (start & 15) * 4;             // fixed channel group base
    atomicAdd(&sh1[cg + 0], s.x);  atomicAdd(&sh1[cg + 1], s.y);
    atomicAdd(&sh1[cg + 2], s.z);  atomicAdd(&sh1[cg + 3], s.w);
    atomicAdd(&sh2[cg + 0], s2.x); atomicAdd(&sh2[cg + 1], s2.y);
    atomicAdd(&sh2[cg + 2], s2.z); atomicAdd(&sh2[cg + 3], s2.w);
    __syncthreads();
    if (threadIdx.x < C_OUT) {
        atomicAdd(&g_sum[threadIdx.x],   sh1[threadIdx.x]);
        atomicAdd(&g_sumsq[threadIdx.x], sh2[threadIdx.x]);
    }
}

// ---------------------------------------------------------------------------
// Pass C: finalize BN affine (bias cancels algebraically).
// ---------------------------------------------------------------------------
__global__ void finalize_stats(const float* __restrict__ gamma,
                               const float* __restrict__ beta,
                               float inv_n)
{
    const int c = threadIdx.x;
    float mean = g_sum[c] * inv_n;
    float var  = g_sumsq[c] * inv_n - mean * mean;
    float a    = gamma[c] * rsqrtf(var + EPS);
    g_a[c] = a;
    g_b[c] = fmaf(-mean, a, beta[c]);
}

// ---------------------------------------------------------------------------
// Pass D: in-place normalize + ReLU, float4-vectorized.
// ---------------------------------------------------------------------------
__global__ void norm_relu(float4* __restrict__ out4, int n4)
{
    const int start  = blockIdx.x * blockDim.x + threadIdx.x;
    const int stride = blockDim.x * gridDim.x;   // multiple of 16
    const int cg = (start & 15) * 4;
    const float4 a = *(const float4*)&g_a[cg];
    const float4 b = *(const float4*)&g_b[cg];
    for (int i = start; i < n4; i += stride) {
        float4 v = out4[i];
        v.x = fmaxf(fmaf(v.x, a.x, b.x), 0.f);
        v.y = fmaxf(fmaf(v.y, a.y, b.y), 0.f);
        v.z = fmaxf(fmaf(v.z, a.z, b.z), 0.f);
        v.w = fmaxf(fmaf(v.w, a.w, b.w), 0.f);
        out4[i] = v;
    }
}

// ---------------------------------------------------------------------------
// Launch. Inputs: x, W, bias, gamma, beta, k_idx, out_idx, num_out.
// ---------------------------------------------------------------------------
extern "C" void kernel_launch(void* const* d_in, const int* in_sizes, int n_in,
                              void* d_out, int out_size)
{
    const float* x     = (const float*)d_in[0];
    const float* W     = (const float*)d_in[1];
    const float* gamma = (const float*)d_in[3];
    const float* beta  = (const float*)d_in[4];
    const int*   kidx  = (const int*)d_in[5];
    const int*   oidx  = (const int*)d_in[6];

    const int n       = in_sizes[0] / C_IN;
    const int total   = out_size;               // num_out * 64
    const int num_out = total / C_OUT;
    const int n4      = total / 4;

    cudaMemsetAsync(d_out, 0, (size_t)total * sizeof(float), 0);

    const int tiles = (n + TILE - 1) / TILE;
    conv_scatter<<<tiles, 256>>>(x, W, kidx, oidx, (float*)d_out, n);
    stats_pass<<<1184, 256>>>((const float4*)d_out, n4);
    finalize_stats<<<1, C_OUT>>>(gamma, beta, 1.0f / (float)num_out);
    norm_relu<<<1184, 256>>>((float4*)d_out, n4);
}